// round 7
// baseline (speedup 1.0000x reference)
#include <cuda_runtime.h>
#include <math.h>
#include <string.h>

#define Nn   50000
#define Ee   500000
#define FIN  64
#define EIN  16
#define Hh   100
#define LL   2
#define BN_EPS 1e-5f

// ---------------- scratch (static device globals; no allocation) -------------
__device__ float g_h   [Nn * Hh];
__device__ float g_e   [(size_t)Ee * Hh];
__device__ float g_agg [Nn * Hh];
__device__ float g_z   [Nn * Hh];
__device__ float g_Ha  [Nn * Hh];
__device__ float g_Hb  [Nn * Hh];
__device__ float g_HRa [Nn * 50];
__device__ float g_HRb [Nn * 50];
__device__ float g_o1  [(size_t)Ee * 50];
__device__ float g_stats[2 * Hh];
__device__ float g_wt  [154600];     // transposed, K-padded weights

// ---------------- weight transpose (once per launch) -------------------------
#define NJOBS 17
struct TransJobs {
    const float* src[NJOBS];
    int K[NJOBS], J[NJOBS], KT[NJOBS], dstOff[NJOBS];
};

__global__ void trans_k(TransJobs tj, float* __restrict__ wt) {
    int job = blockIdx.x;
    const float* s = tj.src[job];
    float* d = wt + tj.dstOff[job];
    int K = tj.K[job], J = tj.J[job], KT = tj.KT[job];
    int n = J * KT;
    for (int idx = threadIdx.x; idx < n; idx += blockDim.x) {
        int j = idx / KT, k = idx - j * KT;
        d[idx] = (k < K) ? s[k * J + j] : 0.f;
    }
}

// zero agg + stats in one launch
__global__ void zero2_k(float* __restrict__ agg, float* __restrict__ st) {
    int i = blockIdx.x * blockDim.x + threadIdx.x;
    if (i < Nn * Hh) agg[i] = 0.f;
    if (i < 2 * Hh) st[i] = 0.f;
}

// ---------------- scatter: warp per edge, float4 -----------------------------
__global__ void __launch_bounds__(256)
scatter_k(const float* __restrict__ h, const float* __restrict__ e,
          const int* __restrict__ src, const int* __restrict__ dst,
          float* __restrict__ agg) {
    int ed = blockIdx.x * 8 + (threadIdx.x >> 5);
    int lane = threadIdx.x & 31;
    if (lane >= 25) return;
    int s = src[ed], d = dst[ed];
    float4 hv = ((const float4*)(h + (size_t)s * Hh))[lane];
    float4 ev = ((const float4*)(e + (size_t)ed * Hh))[lane];
    float* ar = agg + (size_t)d * Hh + 4 * lane;
    float m0 = hv.x + ev.x, m1 = hv.y + ev.y, m2 = hv.z + ev.z, m3 = hv.w + ev.w;
    if (m0 > 0.f) atomicAdd(ar + 0, m0);
    if (m1 > 0.f) atomicAdd(ar + 1, m1);
    if (m2 > 0.f) atomicAdd(ar + 2, m2);
    if (m3 > 0.f) atomicAdd(ar + 3, m3);
}

// h = (h + relu(batchnorm(z))) * 0.5
__global__ void hupd_k(float* __restrict__ h, const float* __restrict__ z,
                       const float* __restrict__ stats,
                       const float* __restrict__ gamma, const float* __restrict__ beta) {
    int idx = blockIdx.x * blockDim.x + threadIdx.x;
    if (idx >= Nn * Hh) return;
    int j = idx % Hh;
    float mu  = stats[j] * (1.0f / Nn);
    float var = fmaf(-mu, mu, stats[Hh + j] * (1.0f / Nn));
    float zn  = (z[idx] - mu) * rsqrtf(var + BN_EPS) * gamma[j] + beta[j];
    h[idx] = (h[idx] + fmaxf(zn, 0.f)) * 0.5f;
}

// ---------------- shared FFMA2 mainloop --------------------------------------
// acc[r][q] (K-split float2) += As[(y+10r)] . Ws[(x+25q)] over C4 16B-chunks.
template<int C4, int JT, int NR>
__device__ __forceinline__ void mma_loop(const float* __restrict__ Ws,
                                         const float* __restrict__ As,
                                         int x, int y,
                                         unsigned long long acc[][JT]) {
    const ulonglong2* WsU = (const ulonglong2*)Ws;
    const ulonglong2* AsU = (const ulonglong2*)As;
    #pragma unroll 3
    for (int c = 0; c < C4; c++) {
        ulonglong2 b[JT];
        #pragma unroll
        for (int q = 0; q < JT; q++) b[q] = WsU[(x + 25 * q) * C4 + c];
        #pragma unroll
        for (int r = 0; r < NR; r++) {
            ulonglong2 a = AsU[(y + 10 * r) * C4 + c];
            #pragma unroll
            for (int q = 0; q < JT; q++) {
                asm("fma.rn.f32x2 %0, %1, %2, %0;" : "+l"(acc[r][q]) : "l"(a.x), "l"(b[q].x));
                asm("fma.rn.f32x2 %0, %1, %2, %0;" : "+l"(acc[r][q]) : "l"(a.y), "l"(b[q].y));
            }
        }
    }
}

// ---------------- single GEMM, 50-row tiles ----------------------------------
// C[M, 25*JT] = op(A)[M,KIN] @ Wt(pre-transposed [JN][KT]) + epilogue
// PRO: 0 plain, 2 relu(A).  EPI: 0 store+bias, 3 relu(acc+bias+Ta[src]+Tb[dst]), 4 raw
template<int KIN, int KT, int JT, int PRO, int EPI>
__global__ void __launch_bounds__(256, 2)
gemm1_k(const float* __restrict__ A, const float* __restrict__ Wt,
        const float* __restrict__ bias, float* __restrict__ C,
        const int* __restrict__ src, const int* __restrict__ dst,
        const float* __restrict__ Ta, const float* __restrict__ Tb) {
    constexpr int JN = 25 * JT;
    constexpr int C4 = KT / 4;
    extern __shared__ float sm[];
    float* Ws = sm;             // [JN][KT]
    float* As = sm + JN * KT;   // [50][KT]
    const int x = threadIdx.x, y = threadIdx.y;
    const int tid = y * 25 + x;
    const int row0 = blockIdx.x * 50;

    for (int idx = tid; idx < JN * KT / 4; idx += 250)
        ((float4*)Ws)[idx] = ((const float4*)Wt)[idx];
    for (int idx = tid; idx < 50 * KIN; idx += 250) {
        int i = idx / KIN, k = idx - i * KIN;
        float v = A[(size_t)(row0 + i) * KIN + k];
        if (PRO == 2) v = fmaxf(v, 0.f);
        As[i * KT + k] = v;
    }
    if (KT > KIN) {
        constexpr int PD = KT - KIN;
        for (int idx = tid; idx < 50 * PD; idx += 250) {
            int i = idx / PD, k = KIN + idx - i * PD;
            As[i * KT + k] = 0.f;
        }
    }
    __syncthreads();

    unsigned long long acc[5][JT];
    #pragma unroll
    for (int r = 0; r < 5; r++)
        #pragma unroll
        for (int q = 0; q < JT; q++) acc[r][q] = 0ULL;

    mma_loop<C4, JT, 5>(Ws, As, x, y, acc);

    #pragma unroll
    for (int r = 0; r < 5; r++) {
        int row = row0 + y + 10 * r;
        const float* ta = nullptr; const float* tb = nullptr;
        if (EPI == 3) {
            ta = Ta + (size_t)src[row] * JN;
            tb = Tb + (size_t)dst[row] * JN;
        }
        #pragma unroll
        for (int q = 0; q < JT; q++) {
            int j = x + 25 * q;
            float2 f;
            memcpy(&f, &acc[r][q], 8);
            float v = f.x + f.y;
            float* cp = C + (size_t)row * JN + j;
            if (EPI == 0)      *cp = v + bias[j];
            else if (EPI == 3) *cp = fmaxf(v + bias[j] + ta[j] + tb[j], 0.f);
            else               *cp = v;
        }
    }
}

// ---------------- fused double GEMM (E- and N-sized MLPs) --------------------
// MODE 0 (gine):  z = relu((h+agg)@W1+b1)@W2+b2 ; store z; accumulate BN stats
// MODE 1 (edge):  t = relu(e@W1+b1+Ta[src]+Tb[dst]) ; e += 0.5*(t@W2+b2)
// 50-row tiles; t overwrites W1's smem after loop1; e-tile stays live in As.
template<int MODE>
__global__ void __launch_bounds__(256, 2)
gemm2x_k(const float* __restrict__ A, const float* __restrict__ A2,
         const float* __restrict__ W1t, const float* __restrict__ b1,
         const float* __restrict__ W2t, const float* __restrict__ b2,
         float* __restrict__ C,
         const int* __restrict__ src, const int* __restrict__ dst,
         const float* __restrict__ Ta, const float* __restrict__ Tb,
         float* __restrict__ stats) {
    constexpr int KT = 108, C4 = 27;
    extern __shared__ float sm[];
    float* Ws1 = sm;            // [100][108], reused as t-tile after loop1
    float* Ws2 = sm + 10800;    // [100][108]
    float* As  = sm + 21600;    // [50][108]  (stays live through loop2)
    float* As2 = sm;            // t-tile alias
    __shared__ float sst[2 * Hh];
    const int x = threadIdx.x, y = threadIdx.y;
    const int tid = y * 25 + x;
    const int row0 = blockIdx.x * 50;

    if (MODE == 0)
        for (int i = tid; i < 2 * Hh; i += 250) sst[i] = 0.f;
    for (int idx = tid; idx < 2700; idx += 250)
        ((float4*)Ws1)[idx] = ((const float4*)W1t)[idx];
    for (int idx = tid; idx < 2700; idx += 250)
        ((float4*)Ws2)[idx] = ((const float4*)W2t)[idx];
    for (int idx = tid; idx < 50 * 100; idx += 250) {
        int i = idx / 100, k = idx - i * 100;
        float v = A[(size_t)(row0 + i) * 100 + k];
        if (MODE == 0) v += A2[(size_t)(row0 + i) * 100 + k];
        As[i * KT + k] = v;
    }
    for (int idx = tid; idx < 50 * 8; idx += 250) {
        int i = idx / 8, k = 100 + idx - i * 8;
        As[i * KT + k] = 0.f;
    }
    __syncthreads();

    unsigned long long acc[5][4];
    #pragma unroll
    for (int r = 0; r < 5; r++)
        #pragma unroll
        for (int q = 0; q < 4; q++) acc[r][q] = 0ULL;
    mma_loop<C4, 4, 5>(Ws1, As, x, y, acc);
    __syncthreads();   // all reads of Ws1 done

    // mid epilogue: t = relu(acc + b1 [+ gathers]) -> As2 (over Ws1)
    #pragma unroll
    for (int r = 0; r < 5; r++) {
        int rl = y + 10 * r;
        int row = row0 + rl;
        const float* ta = nullptr; const float* tb = nullptr;
        if (MODE == 1) {
            ta = Ta + (size_t)src[row] * 100;
            tb = Tb + (size_t)dst[row] * 100;
        }
        #pragma unroll
        for (int q = 0; q < 4; q++) {
            int j = x + 25 * q;
            float2 f;
            memcpy(&f, &acc[r][q], 8);
            float v = f.x + f.y + b1[j];
            if (MODE == 1) v += ta[j] + tb[j];
            As2[rl * KT + j] = fmaxf(v, 0.f);
        }
    }
    for (int idx = tid; idx < 50 * 8; idx += 250) {
        int i = idx / 8, k = 100 + idx - i * 8;
        As2[i * KT + k] = 0.f;
    }
    __syncthreads();

    unsigned long long acc2[5][4];
    #pragma unroll
    for (int r = 0; r < 5; r++)
        #pragma unroll
        for (int q = 0; q < 4; q++) acc2[r][q] = 0ULL;
    mma_loop<C4, 4, 5>(Ws2, As2, x, y, acc2);

    #pragma unroll
    for (int r = 0; r < 5; r++) {
        int rl = y + 10 * r;
        int row = row0 + rl;
        #pragma unroll
        for (int q = 0; q < 4; q++) {
            int j = x + 25 * q;
            float2 f;
            memcpy(&f, &acc2[r][q], 8);
            float v = f.x + f.y + b2[j];
            float* cp = C + (size_t)row * 100 + j;
            if (MODE == 0) {
                *cp = v;
                atomicAdd(&sst[j], v);
                atomicAdd(&sst[Hh + j], v * v);
            } else {
                *cp = fmaf(0.5f, v, As[rl * KT + j]);   // e_old still in As
            }
        }
    }
    if (MODE == 0) {
        __syncthreads();
        for (int i = tid; i < 2 * Hh; i += 250) atomicAdd(&stats[i], sst[i]);
    }
}

// fused tail: out = relu(o1@w2+b2) @ w3 + b3 per edge
__global__ void __launch_bounds__(256)
final_fused_k(const float* __restrict__ o1,
              const float* __restrict__ w2, const float* __restrict__ b2,
              const float* __restrict__ w3, const float* __restrict__ b3,
              float* __restrict__ out) {
    __shared__ float sw2[50 * 25];
    __shared__ float sw3[50];
    __shared__ float sb2[25];
    __shared__ float sb3[2];
    int t = threadIdx.x;
    for (int i = t; i < 1250; i += 256) sw2[i] = w2[i];
    if (t < 50) sw3[t] = w3[t];
    if (t < 25) sb2[t] = b2[t];
    if (t < 2)  sb3[t] = b3[t];
    __syncthreads();
    int r = blockIdx.x * 256 + t;
    if (r >= Ee) return;
    float a[50];
    const float2* row = (const float2*)(o1 + (size_t)r * 50);
    #pragma unroll
    for (int i = 0; i < 25; i++) { float2 v = row[i]; a[2*i] = v.x; a[2*i+1] = v.y; }
    float out0 = sb3[0], out1 = sb3[1];
    #pragma unroll 5
    for (int j = 0; j < 25; j++) {
        float s = sb2[j];
        #pragma unroll
        for (int k = 0; k < 50; k++) s = fmaf(a[k], sw2[k * 25 + j], s);
        s = fmaxf(s, 0.f);
        out0 = fmaf(s, sw3[2 * j],     out0);
        out1 = fmaf(s, sw3[2 * j + 1], out1);
    }
    out[(size_t)r * 2]     = out0;
    out[(size_t)r * 2 + 1] = out1;
}

// ---------------- launcher ---------------------------------------------------
static inline int cdiv(int a, int b) { return (a + b - 1) / b; }

template<int KIN, int KT, int JT, int PRO, int EPI>
static void launch_gemm1(int M, const float* A, const float* Wt,
                         const float* bias, float* C,
                         const int* src = nullptr, const int* dst = nullptr,
                         const float* Ta = nullptr, const float* Tb = nullptr) {
    int smem = (25 * JT) * KT * 4 + 50 * KT * 4;
    cudaFuncSetAttribute(gemm1_k<KIN, KT, JT, PRO, EPI>,
                         cudaFuncAttributeMaxDynamicSharedMemorySize, smem);
    gemm1_k<KIN, KT, JT, PRO, EPI><<<M / 50, dim3(25, 10), smem>>>(
        A, Wt, bias, C, src, dst, Ta, Tb);
}

template<int MODE>
static void launch_gemm2x(int M, const float* A, const float* A2,
                          const float* W1t, const float* b1,
                          const float* W2t, const float* b2, float* C,
                          const int* src, const int* dst,
                          const float* Ta, const float* Tb, float* stats) {
    int smem = (10800 + 10800 + 50 * 108) * 4;
    cudaFuncSetAttribute(gemm2x_k<MODE>,
                         cudaFuncAttributeMaxDynamicSharedMemorySize, smem);
    gemm2x_k<MODE><<<M / 50, dim3(25, 10), smem>>>(
        A, A2, W1t, b1, W2t, b2, C, src, dst, Ta, Tb, stats);
}

extern "C" void kernel_launch(void* const* d_in, const int* in_sizes, int n_in,
                              void* d_out, int out_size) {
    const float* x        = (const float*)d_in[0];
    const float* edge_attr= (const float*)d_in[1];
    const int*   ei       = (const int*)  d_in[2];
    const float* node_w   = (const float*)d_in[3];
    const float* node_b   = (const float*)d_in[4];
    const float* edge_w   = (const float*)d_in[5];
    const float* edge_b   = (const float*)d_in[6];
    const float* gw1      = (const float*)d_in[7];
    const float* gb1      = (const float*)d_in[8];
    const float* gw2      = (const float*)d_in[9];
    const float* gb2      = (const float*)d_in[10];
    const float* bng      = (const float*)d_in[11];
    const float* bnb      = (const float*)d_in[12];
    const float* ew1      = (const float*)d_in[13];
    const float* eb1      = (const float*)d_in[14];
    const float* ew2      = (const float*)d_in[15];
    const float* eb2      = (const float*)d_in[16];
    const float* mw1      = (const float*)d_in[17];
    const float* mb1      = (const float*)d_in[18];
    const float* mw2      = (const float*)d_in[19];
    const float* mb2      = (const float*)d_in[20];
    const float* mw3      = (const float*)d_in[21];
    const float* mb3      = (const float*)d_in[22];
    float* out = (float*)d_out;

    void* p;
    cudaGetSymbolAddress(&p, g_h);    float* h    = (float*)p;
    cudaGetSymbolAddress(&p, g_e);    float* e    = (float*)p;
    cudaGetSymbolAddress(&p, g_agg);  float* agg  = (float*)p;
    cudaGetSymbolAddress(&p, g_z);    float* z    = (float*)p;
    cudaGetSymbolAddress(&p, g_Ha);   float* Ha   = (float*)p;
    cudaGetSymbolAddress(&p, g_Hb);   float* Hb   = (float*)p;
    cudaGetSymbolAddress(&p, g_HRa);  float* HRa  = (float*)p;
    cudaGetSymbolAddress(&p, g_HRb);  float* HRb  = (float*)p;
    cudaGetSymbolAddress(&p, g_o1);   float* o1   = (float*)p;
    cudaGetSymbolAddress(&p, g_stats);float* st   = (float*)p;
    cudaGetSymbolAddress(&p, g_wt);   float* wt   = (float*)p;

    const int* src = ei;
    const int* dst = ei + Ee;

    // ---- transpose weights (1 launch) ----
    const int O_NODE = 0, O_EDGE = 6800, O_GW1 = 8800, O_GW2 = 30400,
              O_EW1 = 52000, O_EW2 = 116800, O_MW1 = 138400;
    TransJobs tj;
    int ji = 0;
    auto addjob = [&](const float* s, int K, int J, int KT, int off) {
        tj.src[ji] = s; tj.K[ji] = K; tj.J[ji] = J; tj.KT[ji] = KT; tj.dstOff[ji] = off; ji++;
    };
    addjob(node_w, 64, 100, 68, O_NODE);
    addjob(edge_w, 16, 100, 20, O_EDGE);
    for (int l = 0; l < 2; l++) addjob(gw1 + l * 10000, 100, 100, 108, O_GW1 + l * 10800);
    for (int l = 0; l < 2; l++) addjob(gw2 + l * 10000, 100, 100, 108, O_GW2 + l * 10800);
    for (int l = 0; l < 2; l++)
        for (int q = 0; q < 3; q++)
            addjob(ew1 + l * 30000 + q * 10000, 100, 100, 108, O_EW1 + (l * 3 + q) * 10800);
    for (int l = 0; l < 2; l++) addjob(ew2 + l * 10000, 100, 100, 108, O_EW2 + l * 10800);
    for (int q = 0; q < 3; q++) addjob(mw1 + q * 5000, 100, 50, 108, O_MW1 + q * 5400);
    trans_k<<<NJOBS, 256>>>(tj, wt);                            // launch 1

    zero2_k<<<cdiv(Nn * Hh, 256), 256>>>(agg, st);              // launch 2
    launch_gemm1<FIN, 68, 4, 0, 0>(Nn, x, wt + O_NODE, node_b, h);          // launch 3
    launch_gemm1<EIN, 20, 4, 0, 0>(Ee, edge_attr, wt + O_EDGE, edge_b, e);  // launch 4 (profiled)

    for (int l = 0; l < LL; l++) {
        if (l > 0) zero2_k<<<cdiv(Nn * Hh, 256), 256>>>(agg, st);
        scatter_k<<<Ee / 8, 256>>>(h, e, src, dst, agg);
        // fused GINE MLP + BN stats
        launch_gemm2x<0>(Nn, h, agg,
                         wt + O_GW1 + l * 10800, gb1 + l * Hh,
                         wt + O_GW2 + l * 10800, gb2 + l * Hh,
                         z, nullptr, nullptr, nullptr, nullptr, st);
        hupd_k<<<cdiv(Nn * Hh, 256), 256>>>(h, z, st, bng + l * Hh, bnb + l * Hh);
        // node-level halves of the edge MLP
        launch_gemm1<100, 108, 4, 0, 4>(Nn, h, wt + O_EW1 + (l * 3 + 0) * 10800, nullptr, Ha);
        launch_gemm1<100, 108, 4, 0, 4>(Nn, h, wt + O_EW1 + (l * 3 + 1) * 10800, nullptr, Hb);
        // fused: t = relu(e@Wc + Ha[src] + Hb[dst] + b1); e += 0.5*(t@W2 + b2)
        launch_gemm2x<1>(Ee, e, nullptr,
                         wt + O_EW1 + (l * 3 + 2) * 10800, eb1 + l * Hh,
                         wt + O_EW2 + l * 10800, eb2 + l * Hh,
                         e, src, dst, Ha, Hb, nullptr);
    }

    // readout (node-level decomposition of mlp_w1)
    launch_gemm1<100, 108, 2, 2, 4>(Nn, h, wt + O_MW1,        nullptr, HRa);
    launch_gemm1<100, 108, 2, 2, 4>(Nn, h, wt + O_MW1 + 5400, nullptr, HRb);
    launch_gemm1<100, 108, 2, 0, 3>(Ee, e, wt + O_MW1 + 10800, mb1, o1, src, dst, HRa, HRb);
    final_fused_k<<<cdiv(Ee, 256), 256>>>(o1, mw2, mb2, mw3, mb3, out);
}

// round 8
// speedup vs baseline: 2.5641x; 2.5641x over previous
#include <cuda_runtime.h>
#include <math.h>

#define Nn   50000
#define Ee   500000
#define FIN  64
#define EIN  16
#define Hh   100
#define LL   2
#define BN_EPS 1e-5f

// ---------------- scratch (static device globals; no allocation) -------------
__device__ float g_h   [Nn * Hh];
__device__ float g_e   [(size_t)Ee * Hh];
__device__ float g_agg [Nn * Hh];
__device__ float g_zin [Nn * Hh];          // also reused as relu(h) at readout
__device__ float g_t   [Nn * Hh];
__device__ float g_z   [Nn * Hh];
__device__ float g_Ha  [Nn * Hh];
__device__ float g_Hb  [Nn * Hh];
__device__ float g_HRa [Nn * 50];
__device__ float g_HRb [Nn * 50];
__device__ float g_t1  [(size_t)Ee * Hh];
__device__ float g_o1  [(size_t)Ee * 50];
__device__ float g_stats[2 * Hh];

// ---------------- small kernels ----------------------------------------------
__global__ void zero2_k(float* __restrict__ agg, float* __restrict__ st) {
    int i = blockIdx.x * blockDim.x + threadIdx.x;
    if (i < Nn * Hh) agg[i] = 0.f;
    if (i < 2 * Hh) st[i] = 0.f;
}

__global__ void add_k(const float* __restrict__ a, const float* __restrict__ b,
                      float* __restrict__ c, int n) {
    int i = blockIdx.x * blockDim.x + threadIdx.x;
    if (i < n) c[i] = a[i] + b[i];
}

__global__ void relu_k(const float* __restrict__ a, float* __restrict__ c, int n) {
    int i = blockIdx.x * blockDim.x + threadIdx.x;
    if (i < n) c[i] = fmaxf(a[i], 0.f);
}

// msg = relu(h[src] + e) scatter-added into agg[dst]; warp per edge, float4
__global__ void __launch_bounds__(256)
scatter_k(const float* __restrict__ h, const float* __restrict__ e,
          const int* __restrict__ src, const int* __restrict__ dst,
          float* __restrict__ agg) {
    int ed = blockIdx.x * 8 + (threadIdx.x >> 5);
    int lane = threadIdx.x & 31;
    if (lane >= 25) return;
    int s = src[ed], d = dst[ed];
    float4 hv = ((const float4*)(h + (size_t)s * Hh))[lane];
    float4 ev = ((const float4*)(e + (size_t)ed * Hh))[lane];
    float* ar = agg + (size_t)d * Hh + 4 * lane;
    float m0 = hv.x + ev.x, m1 = hv.y + ev.y, m2 = hv.z + ev.z, m3 = hv.w + ev.w;
    if (m0 > 0.f) atomicAdd(ar + 0, m0);
    if (m1 > 0.f) atomicAdd(ar + 1, m1);
    if (m2 > 0.f) atomicAdd(ar + 2, m2);
    if (m3 > 0.f) atomicAdd(ar + 3, m3);
}

__global__ void bn_stats_k(const float* __restrict__ z, float* __restrict__ stats) {
    int j = threadIdx.x;
    if (j >= Hh) return;
    int r0 = blockIdx.x * 256;
    int r1 = min(r0 + 256, Nn);
    float s = 0.f, ss = 0.f;
    for (int r = r0; r < r1; r++) {
        float v = z[(size_t)r * Hh + j];
        s += v;
        ss = fmaf(v, v, ss);
    }
    atomicAdd(&stats[j], s);
    atomicAdd(&stats[Hh + j], ss);
}

__global__ void hupd_k(float* __restrict__ h, const float* __restrict__ z,
                       const float* __restrict__ stats,
                       const float* __restrict__ gamma, const float* __restrict__ beta) {
    int idx = blockIdx.x * blockDim.x + threadIdx.x;
    if (idx >= Nn * Hh) return;
    int j = idx % Hh;
    float mu  = stats[j] * (1.0f / Nn);
    float var = fmaf(-mu, mu, stats[Hh + j] * (1.0f / Nn));
    float zn  = (z[idx] - mu) * rsqrtf(var + BN_EPS) * gamma[j] + beta[j];
    h[idx] = (h[idx] + fmaxf(zn, 0.f)) * 0.5f;
}

// ---------------- TF32 tensor-core GEMM --------------------------------------
// C[M, NV] = A[M, KIN] @ W[KIN, NV] (+ epilogue), via mma.sync.m16n8k8 tf32.
// Persistent grid; W packed ONCE per block into smem as per-lane b-fragments;
// A tiles (64 rows) double-buffered via cp.async; warp = 16 rows.
// EPI: 0 store+bias, 1 relu(acc+bias), 2 C += 0.5*(acc+bias),
//      3 relu(acc+bias+Ta[src[row]]+Tb[dst[row]]), 4 raw store
__device__ __forceinline__ unsigned f2tf(float f) {
    unsigned u;
    asm("cvt.rna.tf32.f32 %0, %1;" : "=r"(u) : "f"(f));
    return u;
}

template<int KIN, int KST, int KP, int NT, int NV, int EPI>
__global__ void __launch_bounds__(128, 2)
tgemm_k(const float* __restrict__ A, const float* __restrict__ W,
        const float* __restrict__ bias, float* __restrict__ C, int M,
        const int* __restrict__ src, const int* __restrict__ dst,
        const float* __restrict__ Ta, const float* __restrict__ Tb) {
    constexpr int WFRAG = KST * NT * 64;    // floats of packed W frags
    constexpr int ATILE = 64 * KP;          // floats per A buffer
    constexpr int CH    = KP / 4;           // 16B chunks per row
    extern __shared__ float sm[];
    float* Wp = sm;
    float* As = sm + WFRAG;
    const int tid  = threadIdx.x;
    const int lane = tid & 31, warp = tid >> 5;
    const int g = lane >> 2, tg = lane & 3;

    // pack W fragments (tf32-rounded): b0=W[k][n], b1=W[k+4][n]
    for (int idx = tid; idx < KST * NT * 32; idx += 128) {
        int ks  = idx / (NT * 32);
        int rem = idx - ks * NT * 32;
        int nt = rem >> 5, l = rem & 31;
        int k0 = ks * 8 + (l & 3), n = nt * 8 + (l >> 2);
        float b0 = (k0 < KIN && n < NV) ? W[k0 * NV + n] : 0.f;
        float b1 = (k0 + 4 < KIN && n < NV) ? W[(k0 + 4) * NV + n] : 0.f;
        ((float2*)Wp)[idx] = make_float2(__uint_as_float(f2tf(b0)),
                                         __uint_as_float(f2tf(b1)));
    }

    const int ntile = (M + 63) >> 6;

    auto prefetch = [&](int t, int buf) {
        float* db = As + buf * ATILE;
        const int row0 = t * 64;
        for (int idx = tid; idx < 64 * CH; idx += 128) {
            int r = idx / CH, c = idx - r * CH;
            int grow = row0 + r;
            unsigned sa = (unsigned)__cvta_generic_to_shared(db + r * KP + c * 4);
            int nb = 0;
            const float* gs = A;
            if (grow < M) {
                int col = c * 4;
                nb = KIN - col;
                nb = nb < 0 ? 0 : (nb > 4 ? 4 : nb);
                nb *= 4;
                gs = A + (size_t)grow * KIN + (col < KIN ? col : 0);
            }
            asm volatile("cp.async.cg.shared.global [%0], [%1], 16, %2;"
                         :: "r"(sa), "l"(gs), "r"(nb));
        }
        asm volatile("cp.async.commit_group;");
    };

    if (blockIdx.x >= ntile) return;
    prefetch(blockIdx.x, 0);
    __syncthreads();   // Wp ready (and first tile committed)

    int buf = 0;
    for (int t = blockIdx.x; t < ntile; t += gridDim.x) {
        int tn = t + gridDim.x;
        if (tn < ntile) {
            prefetch(tn, buf ^ 1);
            asm volatile("cp.async.wait_group 1;");
        } else {
            asm volatile("cp.async.wait_group 0;");
        }
        __syncthreads();

        const float* Ab = As + buf * ATILE + warp * 16 * KP;
        float acc[NT][4];
        #pragma unroll
        for (int nt = 0; nt < NT; nt++) {
            acc[nt][0] = 0.f; acc[nt][1] = 0.f; acc[nt][2] = 0.f; acc[nt][3] = 0.f;
        }

        #pragma unroll
        for (int ks = 0; ks < KST; ks++) {
            unsigned a0 = f2tf(Ab[g * KP + ks * 8 + tg]);
            unsigned a1 = f2tf(Ab[(g + 8) * KP + ks * 8 + tg]);
            unsigned a2 = f2tf(Ab[g * KP + ks * 8 + tg + 4]);
            unsigned a3 = f2tf(Ab[(g + 8) * KP + ks * 8 + tg + 4]);
            const float2* wrow = (const float2*)Wp + ks * NT * 32 + lane;
            #pragma unroll
            for (int nt = 0; nt < NT; nt++) {
                float2 b = wrow[nt * 32];
                asm volatile(
                    "mma.sync.aligned.m16n8k8.row.col.f32.tf32.tf32.f32 "
                    "{%0,%1,%2,%3}, {%4,%5,%6,%7}, {%8,%9}, {%0,%1,%2,%3};"
                    : "+f"(acc[nt][0]), "+f"(acc[nt][1]),
                      "+f"(acc[nt][2]), "+f"(acc[nt][3])
                    : "r"(a0), "r"(a1), "r"(a2), "r"(a3),
                      "r"(__float_as_uint(b.x)), "r"(__float_as_uint(b.y)));
            }
        }

        // epilogue
        int rbase = t * 64 + warp * 16;
        #pragma unroll
        for (int half = 0; half < 2; half++) {
            int row = rbase + g + half * 8;
            bool rok = row < M;
            const float* ta = nullptr; const float* tb = nullptr;
            if (EPI == 3 && rok) {
                ta = Ta + (size_t)src[row] * NV;
                tb = Tb + (size_t)dst[row] * NV;
            }
            #pragma unroll
            for (int nt = 0; nt < NT; nt++) {
                int n = nt * 8 + tg * 2;
                if (rok && n < NV) {
                    float v0 = acc[nt][half * 2 + 0];
                    float v1 = acc[nt][half * 2 + 1];
                    float2* cp = (float2*)(C + (size_t)row * NV + n);
                    if (EPI == 0) {
                        float2 bs = *(const float2*)(bias + n);
                        *cp = make_float2(v0 + bs.x, v1 + bs.y);
                    } else if (EPI == 1) {
                        float2 bs = *(const float2*)(bias + n);
                        *cp = make_float2(fmaxf(v0 + bs.x, 0.f), fmaxf(v1 + bs.y, 0.f));
                    } else if (EPI == 2) {
                        float2 bs = *(const float2*)(bias + n);
                        float2 old = *cp;
                        *cp = make_float2(fmaf(0.5f, v0 + bs.x, old.x),
                                          fmaf(0.5f, v1 + bs.y, old.y));
                    } else if (EPI == 3) {
                        float2 bs = *(const float2*)(bias + n);
                        float2 tav = *(const float2*)(ta + n);
                        float2 tbv = *(const float2*)(tb + n);
                        *cp = make_float2(fmaxf(v0 + bs.x + tav.x + tbv.x, 0.f),
                                          fmaxf(v1 + bs.y + tav.y + tbv.y, 0.f));
                    } else {
                        *cp = make_float2(v0, v1);
                    }
                }
            }
        }
        buf ^= 1;
        __syncthreads();   // compute done before this buffer is re-filled
    }
}

// fused tail: out = relu(o1@w2+b2) @ w3 + b3 per edge
__global__ void __launch_bounds__(256)
final_fused_k(const float* __restrict__ o1,
              const float* __restrict__ w2, const float* __restrict__ b2,
              const float* __restrict__ w3, const float* __restrict__ b3,
              float* __restrict__ out) {
    __shared__ float sw2[50 * 25];
    __shared__ float sw3[50];
    __shared__ float sb2[25];
    __shared__ float sb3[2];
    int t = threadIdx.x;
    for (int i = t; i < 1250; i += 256) sw2[i] = w2[i];
    if (t < 50) sw3[t] = w3[t];
    if (t < 25) sb2[t] = b2[t];
    if (t < 2)  sb3[t] = b3[t];
    __syncthreads();
    int r = blockIdx.x * 256 + t;
    if (r >= Ee) return;
    float a[50];
    const float2* row = (const float2*)(o1 + (size_t)r * 50);
    #pragma unroll
    for (int i = 0; i < 25; i++) { float2 v = row[i]; a[2*i] = v.x; a[2*i+1] = v.y; }
    float out0 = sb3[0], out1 = sb3[1];
    #pragma unroll 5
    for (int j = 0; j < 25; j++) {
        float s = sb2[j];
        #pragma unroll
        for (int k = 0; k < 50; k++) s = fmaf(a[k], sw2[k * 25 + j], s);
        s = fmaxf(s, 0.f);
        out0 = fmaf(s, sw3[2 * j],     out0);
        out1 = fmaf(s, sw3[2 * j + 1], out1);
    }
    out[(size_t)r * 2]     = out0;
    out[(size_t)r * 2 + 1] = out1;
}

// ---------------- launcher ---------------------------------------------------
static inline int cdiv(int a, int b) { return (a + b - 1) / b; }

template<int KIN, int KST, int KP, int NT, int NV, int EPI>
static void launch_tgemm(int M, const float* A, const float* W,
                         const float* bias, float* C,
                         const int* src = nullptr, const int* dst = nullptr,
                         const float* Ta = nullptr, const float* Tb = nullptr) {
    int smem = (KST * NT * 64 + 2 * 64 * KP) * 4;
    cudaFuncSetAttribute(tgemm_k<KIN, KST, KP, NT, NV, EPI>,
                         cudaFuncAttributeMaxDynamicSharedMemorySize, smem);
    int ntile = cdiv(M, 64);
    int grid = ntile < 296 ? ntile : 296;
    tgemm_k<KIN, KST, KP, NT, NV, EPI><<<grid, 128, smem>>>(
        A, W, bias, C, M, src, dst, Ta, Tb);
}

extern "C" void kernel_launch(void* const* d_in, const int* in_sizes, int n_in,
                              void* d_out, int out_size) {
    const float* x        = (const float*)d_in[0];
    const float* edge_attr= (const float*)d_in[1];
    const int*   ei       = (const int*)  d_in[2];
    const float* node_w   = (const float*)d_in[3];
    const float* node_b   = (const float*)d_in[4];
    const float* edge_w   = (const float*)d_in[5];
    const float* edge_b   = (const float*)d_in[6];
    const float* gw1      = (const float*)d_in[7];
    const float* gb1      = (const float*)d_in[8];
    const float* gw2      = (const float*)d_in[9];
    const float* gb2      = (const float*)d_in[10];
    const float* bng      = (const float*)d_in[11];
    const float* bnb      = (const float*)d_in[12];
    const float* ew1      = (const float*)d_in[13];
    const float* eb1      = (const float*)d_in[14];
    const float* ew2      = (const float*)d_in[15];
    const float* eb2      = (const float*)d_in[16];
    const float* mw1      = (const float*)d_in[17];
    const float* mb1      = (const float*)d_in[18];
    const float* mw2      = (const float*)d_in[19];
    const float* mb2      = (const float*)d_in[20];
    const float* mw3      = (const float*)d_in[21];
    const float* mb3      = (const float*)d_in[22];
    float* out = (float*)d_out;

    void* p;
    cudaGetSymbolAddress(&p, g_h);    float* h    = (float*)p;
    cudaGetSymbolAddress(&p, g_e);    float* e    = (float*)p;
    cudaGetSymbolAddress(&p, g_agg);  float* agg  = (float*)p;
    cudaGetSymbolAddress(&p, g_zin);  float* zin  = (float*)p;
    cudaGetSymbolAddress(&p, g_t);    float* t    = (float*)p;
    cudaGetSymbolAddress(&p, g_z);    float* z    = (float*)p;
    cudaGetSymbolAddress(&p, g_Ha);   float* Ha   = (float*)p;
    cudaGetSymbolAddress(&p, g_Hb);   float* Hb   = (float*)p;
    cudaGetSymbolAddress(&p, g_HRa);  float* HRa  = (float*)p;
    cudaGetSymbolAddress(&p, g_HRb);  float* HRb  = (float*)p;
    cudaGetSymbolAddress(&p, g_t1);   float* t1   = (float*)p;
    cudaGetSymbolAddress(&p, g_o1);   float* o1   = (float*)p;
    cudaGetSymbolAddress(&p, g_stats);float* st   = (float*)p;

    const int* src = ei;
    const int* dst = ei + Ee;

    zero2_k<<<cdiv(Nn * Hh, 256), 256>>>(agg, st);                          // 1
    // embeddings: h = x@node_w+b (K=64), e = ea@edge_w+b (K=16)
    launch_tgemm<FIN, 8, 68, 13, 100, 0>(Nn, x, node_w, node_b, h);         // 2
    launch_tgemm<EIN, 2, 20, 13, 100, 0>(Ee, edge_attr, edge_w, edge_b, e); // 3

    for (int l = 0; l < LL; l++) {
        if (l > 0) zero2_k<<<cdiv(Nn * Hh, 256), 256>>>(agg, st);
        scatter_k<<<Ee / 8, 256>>>(h, e, src, dst, agg);                    // 4
        add_k<<<cdiv(Nn * Hh, 256), 256>>>(h, agg, zin, Nn * Hh);           // 5
        // GINE MLP
        launch_tgemm<100, 13, 108, 13, 100, 1>(Nn, zin, gw1 + (size_t)l * 10000,
                                               gb1 + l * Hh, t);            // 6 (profiled)
        launch_tgemm<100, 13, 108, 13, 100, 0>(Nn, t, gw2 + (size_t)l * 10000,
                                               gb2 + l * Hh, z);
        bn_stats_k<<<cdiv(Nn, 256), 128>>>(z, st);
        hupd_k<<<cdiv(Nn * Hh, 256), 256>>>(h, z, st, bng + l * Hh, bnb + l * Hh);
        // edge-MLP decomposed to node level
        launch_tgemm<100, 13, 108, 13, 100, 4>(Nn, h, ew1 + (size_t)l * 30000, nullptr, Ha);
        launch_tgemm<100, 13, 108, 13, 100, 4>(Nn, h, ew1 + (size_t)l * 30000 + 10000, nullptr, Hb);
        // t1 = relu(e@Wc + Ha[src] + Hb[dst] + b1)
        launch_tgemm<100, 13, 108, 13, 100, 3>(Ee, e, ew1 + (size_t)l * 30000 + 20000,
                                               eb1 + l * Hh, t1, src, dst, Ha, Hb);
        // e += 0.5*(t1@ew2 + b2)
        launch_tgemm<100, 13, 108, 13, 100, 2>(Ee, t1, ew2 + (size_t)l * 10000,
                                               eb2 + l * Hh, e);
    }

    // readout (node-level decomposition of mlp_w1; N=50)
    relu_k<<<cdiv(Nn * Hh, 256), 256>>>(h, zin, Nn * Hh);
    launch_tgemm<100, 13, 108, 7, 50, 4>(Nn, zin, mw1,        nullptr, HRa);
    launch_tgemm<100, 13, 108, 7, 50, 4>(Nn, zin, mw1 + 5000, nullptr, HRb);
    launch_tgemm<100, 13, 108, 7, 50, 3>(Ee, e, mw1 + 10000, mb1, o1, src, dst, HRa, HRb);
    final_fused_k<<<cdiv(Ee, 256), 256>>>(o1, mw2, mb2, mw3, mb3, out);
}